// round 6
// baseline (speedup 1.0000x reference)
#include <cuda_runtime.h>
#include <cuda_bf16.h>

namespace {

constexpr int B = 4096;
constexpr int C = 256;
constexpr int R = 2;        // batch rows per thread
constexpr int TB = 128;     // threads per block (half the circuits)

// Closed-form Pauli expansion of the NQ=4, L=2 BasicEntanglerLayers circuit.
// U = E * RX(w1) * E * RX(x + w0) on |0000>, E = CNOT ring (0,1)(1,2)(2,3)(3,0).
// R=2 + 128-thread blocks: small natural register footprint -> high occupancy
// without forcing a cap (R5's 32-reg cap spilled and regressed).
__global__ void __launch_bounds__(TB)
qlin(const float* __restrict__ x, const float* __restrict__ w,
     float* __restrict__ out) {
  const int c  = ((blockIdx.x & 1) ? TB : 0) + threadIdx.x;  // circuit 0..255
  const int b0 = (blockIdx.x >> 1) * R;                      // first batch row

  // Front-batched independent DRAM loads (MLP = R).
  float4 xr[R];
#pragma unroll
  for (int r = 0; r < R; ++r)
    xr[r] = *reinterpret_cast<const float4*>(x + (size_t)(b0 + r) * (C * 4) + c * 4);

  const float4 w0 = *reinterpret_cast<const float4*>(w + c * 8);   // L2-hot
  const float4 w1 = *reinterpret_cast<const float4*>(w + c * 8 + 4);

  // Per-circuit (weight-only) trig — amortized over R rows.
  float s0, c0, s1, c1, s2, c2, s3, c3;
  __sincosf(w1.x, &s0, &c0);
  __sincosf(w1.y, &s1, &c1);
  __sincosf(w1.z, &s2, &c2);
  __sincosf(w1.w, &s3, &c3);

  const float A = c0 * c1, Bv = s0 * s1, P = c0 * s1, Q = s0 * c1;
  const float D = c1 * c2, E = s1 * s2, F = c2 * c3, G = s2 * s3;

#pragma unroll
  for (int r = 0; r < R; ++r) {
    // Data trig: phi_q = x_q + w0_q (embedding RX fused with layer-1 RX).
    float S0, C0, S1, C1, S2, C2, S3, C3;
    __sincosf(xr[r].x + w0.x, &S0, &C0);
    __sincosf(xr[r].y + w0.y, &S1, &C1);
    __sincosf(xr[r].z + w0.z, &S2, &C2);
    __sincosf(xr[r].w + w0.w, &S3, &C3);

    const float C02 = C0 * C2, S02 = S0 * S2;
    const float SC  = S0 * C2, CS  = C0 * S2;
    const float C13 = C1 * C3, S13 = S1 * S3;

    const float u = fmaf(A, C02, Bv * S02);
    const float v = fmaf(P, SC, Q * CS);
    const float Z1 = C3 * u;
    const float Z3 = fmaf(F, u, G * v);

    const float t1 = fmaf(c3, C0 * C13, s3 * (S0 * S13));
    const float t2 = fmaf(c3, C0 * S13, s3 * (S0 * C13));
    const float Z0 = fmaf(D, t1, E * t2);

    const float Z2 = c0 * fmaf(D, C13, E * S13);

    // Store immediately — keeps register live-range short.
    *reinterpret_cast<float4*>(out + (size_t)(b0 + r) * (C * 4) + c * 4) =
        make_float4(Z0, Z1, Z2, Z3);
  }
}

}  // namespace

extern "C" void kernel_launch(void* const* d_in, const int* in_sizes, int n_in,
                              void* d_out, int out_size) {
  (void)in_sizes; (void)n_in; (void)out_size;
  const float* x = reinterpret_cast<const float*>(d_in[0]);
  const float* w = reinterpret_cast<const float*>(d_in[1]);
  float* out = reinterpret_cast<float*>(d_out);
  qlin<<<(B / R) * (C / TB), TB>>>(x, w, out);
}

// round 11
// speedup vs baseline: 1.2294x; 1.2294x over previous
#include <cuda_runtime.h>
#include <cuda_bf16.h>

namespace {

constexpr int B  = 4096;
constexpr int C  = 256;
constexpr int R  = 4;     // batch rows per thread (best weight-trig amortization)
constexpr int TB = 128;   // small blocks: 12 co-resident/SM at ~40 regs, fine tail

// Closed-form Pauli expansion of the NQ=4, L=2 BasicEntanglerLayers circuit.
// U = E * RX(w1) * E * RX(x + w0) on |0000>, E = CNOT ring (0,1)(1,2)(2,3)(3,0).
__global__ void __launch_bounds__(TB)
qlin(const float* __restrict__ x, const float* __restrict__ w,
     float* __restrict__ out) {
  // blockIdx.x: [0, (B/R)*(C/TB)) ; low bit selects circuit half, rest = row group.
  const int c   = ((blockIdx.x & 1) ? TB : 0) + threadIdx.x;   // circuit 0..255
  const int b0  = (blockIdx.x >> 1) * R;                       // first batch row
  const unsigned base = (unsigned)b0 * (C * 4) + (unsigned)c * 4;  // 32-bit offsets

  // Front-batched independent DRAM loads (MLP = R), pointer-walk addressing.
  float4 xr[R];
  {
    const float* xp = x + base;
#pragma unroll
    for (int r = 0; r < R; ++r) {
      xr[r] = *reinterpret_cast<const float4*>(xp);
      xp += C * 4;                          // +1 batch row = 1024 floats
    }
  }

  const float4 w0 = *reinterpret_cast<const float4*>(w + c * 8);   // L2-hot
  const float4 w1 = *reinterpret_cast<const float4*>(w + c * 8 + 4);

  // Per-circuit (weight-only) trig — amortized over R=4 rows.
  float s0, c0, s1, c1, s2, c2, s3, c3;
  __sincosf(w1.x, &s0, &c0);
  __sincosf(w1.y, &s1, &c1);
  __sincosf(w1.z, &s2, &c2);
  __sincosf(w1.w, &s3, &c3);

  const float A = c0 * c1, Bv = s0 * s1, P = c0 * s1, Q = s0 * c1;
  const float D = c1 * c2, E = s1 * s2, F = c2 * c3, G = s2 * s3;

  float* op = out + base;
#pragma unroll
  for (int r = 0; r < R; ++r) {
    // Data trig: phi_q = x_q + w0_q (embedding RX fused with layer-1 RX).
    float S0, C0, S1, C1, S2, C2, S3, C3;
    __sincosf(xr[r].x + w0.x, &S0, &C0);
    __sincosf(xr[r].y + w0.y, &S1, &C1);
    __sincosf(xr[r].z + w0.z, &S2, &C2);
    __sincosf(xr[r].w + w0.w, &S3, &C3);

    const float C02 = C0 * C2, S02 = S0 * S2;
    const float SC  = S0 * C2, CS  = C0 * S2;
    const float C13 = C1 * C3, S13 = S1 * S3;

    const float u = fmaf(A, C02, Bv * S02);
    const float v = fmaf(P, SC, Q * CS);
    const float Z1 = C3 * u;
    const float Z3 = fmaf(F, u, G * v);

    const float t1 = fmaf(c3, C0 * C13, s3 * (S0 * S13));
    const float t2 = fmaf(c3, C0 * S13, s3 * (S0 * C13));
    const float Z0 = fmaf(D, t1, E * t2);

    const float Z2 = c0 * fmaf(D, C13, E * S13);

    *reinterpret_cast<float4*>(op) = make_float4(Z0, Z1, Z2, Z3);
    op += C * 4;                            // next batch row
  }
}

}  // namespace

extern "C" void kernel_launch(void* const* d_in, const int* in_sizes, int n_in,
                              void* d_out, int out_size) {
  (void)in_sizes; (void)n_in; (void)out_size;
  const float* x = reinterpret_cast<const float*>(d_in[0]);
  const float* w = reinterpret_cast<const float*>(d_in[1]);
  float* out = reinterpret_cast<float*>(d_out);
  qlin<<<(B / R) * (C / TB), TB>>>(x, w, out);
}

// round 14
// speedup vs baseline: 1.2657x; 1.0295x over previous
#include <cuda_runtime.h>
#include <cuda_bf16.h>

namespace {

constexpr int B  = 4096;
constexpr int C  = 256;
constexpr int R  = 4;     // rows per thread = 2 packed f32x2 pairs
constexpr int TB = 256;

// ---- f32x2 packed helpers (sm_103a; ptxas never emits these from C++) ----
__device__ __forceinline__ unsigned long long pk2(float lo, float hi) {
  unsigned long long r;
  asm("mov.b64 %0, {%1, %2};" : "=l"(r) : "f"(lo), "f"(hi));
  return r;
}
__device__ __forceinline__ unsigned long long dup2(float v) { return pk2(v, v); }
__device__ __forceinline__ void upk2(unsigned long long v, float& lo, float& hi) {
  asm("mov.b64 {%0, %1}, %2;" : "=f"(lo), "=f"(hi) : "l"(v));
}
__device__ __forceinline__ unsigned long long mul2(unsigned long long a,
                                                   unsigned long long b) {
  unsigned long long r;
  asm("mul.rn.f32x2 %0, %1, %2;" : "=l"(r) : "l"(a), "l"(b));
  return r;
}
__device__ __forceinline__ unsigned long long fma2(unsigned long long a,
                                                   unsigned long long b,
                                                   unsigned long long c) {
  unsigned long long r;
  asm("fma.rn.f32x2 %0, %1, %2, %3;" : "=l"(r) : "l"(a), "l"(b), "l"(c));
  return r;
}

// Closed-form Pauli expansion of the NQ=4, L=2 BasicEntanglerLayers circuit.
// U = E * RX(w1) * E * RX(x + w0) on |0000>, E = CNOT ring (0,1)(1,2)(2,3)(3,0).
// Two batch rows are evaluated per packed f32x2 lane-pair.
__global__ void __launch_bounds__(TB)
qlin(const float* __restrict__ x, const float* __restrict__ w,
     float* __restrict__ out) {
  const int c  = threadIdx.x;           // circuit 0..255
  const int b0 = blockIdx.x * R;        // first batch row
  const unsigned base = (unsigned)b0 * (C * 4) + (unsigned)c * 4;

  // Front-batched independent DRAM loads (MLP = R).
  float4 xr[R];
  {
    const float* xp = x + base;
#pragma unroll
    for (int r = 0; r < R; ++r) { xr[r] = *reinterpret_cast<const float4*>(xp); xp += C * 4; }
  }

  const float4 w0 = *reinterpret_cast<const float4*>(w + c * 8);   // L2-hot
  const float4 w1 = *reinterpret_cast<const float4*>(w + c * 8 + 4);

  // Per-circuit weight trig (amortized over R rows).
  float s0, c0, s1, c1, s2, c2, s3, c3;
  __sincosf(w1.x, &s0, &c0);
  __sincosf(w1.y, &s1, &c1);
  __sincosf(w1.z, &s2, &c2);
  __sincosf(w1.w, &s3, &c3);

  // Packed (duplicated) weight coefficients, built once per thread.
  const unsigned long long Ap  = dup2(c0 * c1), Bp = dup2(s0 * s1);
  const unsigned long long Pp  = dup2(c0 * s1), Qp = dup2(s0 * c1);
  const unsigned long long Dp  = dup2(c1 * c2), Ep = dup2(s1 * s2);
  const unsigned long long Fp  = dup2(c2 * c3), Gp = dup2(s2 * s3);
  const unsigned long long c0p = dup2(c0), c3p = dup2(c3), s3p = dup2(s3);

  float* op = out + base;
#pragma unroll
  for (int p = 0; p < R / 2; ++p) {
    const float4 xa = xr[2 * p], xb = xr[2 * p + 1];

    // Scalar data trig for both rows of the pair (phi = x + w0).
    float Sa0, Ca0, Sa1, Ca1, Sa2, Ca2, Sa3, Ca3;
    float Sb0, Cb0, Sb1, Cb1, Sb2, Cb2, Sb3, Cb3;
    __sincosf(xa.x + w0.x, &Sa0, &Ca0);
    __sincosf(xa.y + w0.y, &Sa1, &Ca1);
    __sincosf(xa.z + w0.z, &Sa2, &Ca2);
    __sincosf(xa.w + w0.w, &Sa3, &Ca3);
    __sincosf(xb.x + w0.x, &Sb0, &Cb0);
    __sincosf(xb.y + w0.y, &Sb1, &Cb1);
    __sincosf(xb.z + w0.z, &Sb2, &Cb2);
    __sincosf(xb.w + w0.w, &Sb3, &Cb3);

    // Pack rows (a, b) lane-wise.
    const unsigned long long C0 = pk2(Ca0, Cb0), S0 = pk2(Sa0, Sb0);
    const unsigned long long C1 = pk2(Ca1, Cb1), S1 = pk2(Sa1, Sb1);
    const unsigned long long C2 = pk2(Ca2, Cb2), S2 = pk2(Sa2, Sb2);
    const unsigned long long C3 = pk2(Ca3, Cb3), S3 = pk2(Sa3, Sb3);

    // Packed bilinear forms (identical algebra to the scalar version).
    const unsigned long long C02 = mul2(C0, C2), S02 = mul2(S0, S2);
    const unsigned long long SC  = mul2(S0, C2), CS  = mul2(C0, S2);
    const unsigned long long C13 = mul2(C1, C3), S13 = mul2(S1, S3);

    const unsigned long long u  = fma2(Ap, C02, mul2(Bp, S02));
    const unsigned long long v  = fma2(Pp, SC,  mul2(Qp, CS));
    const unsigned long long Z1 = mul2(C3, u);
    const unsigned long long Z3 = fma2(Fp, u, mul2(Gp, v));

    const unsigned long long X1 = mul2(C0, C13), X2 = mul2(S0, S13);
    const unsigned long long X3 = mul2(C0, S13), X4 = mul2(S0, C13);
    const unsigned long long t1 = fma2(c3p, X1, mul2(s3p, X2));
    const unsigned long long t2 = fma2(c3p, X3, mul2(s3p, X4));
    const unsigned long long Z0 = fma2(Dp, t1, mul2(Ep, t2));

    const unsigned long long Z2 = mul2(c0p, fma2(Dp, C13, mul2(Ep, S13)));

    // Unpack and store both rows (STG.128 each).
    float z0a, z0b, z1a, z1b, z2a, z2b, z3a, z3b;
    upk2(Z0, z0a, z0b); upk2(Z1, z1a, z1b);
    upk2(Z2, z2a, z2b); upk2(Z3, z3a, z3b);

    *reinterpret_cast<float4*>(op)         = make_float4(z0a, z1a, z2a, z3a);
    *reinterpret_cast<float4*>(op + C * 4) = make_float4(z0b, z1b, z2b, z3b);
    op += 2 * C * 4;
  }
}

}  // namespace

extern "C" void kernel_launch(void* const* d_in, const int* in_sizes, int n_in,
                              void* d_out, int out_size) {
  (void)in_sizes; (void)n_in; (void)out_size;
  const float* x = reinterpret_cast<const float*>(d_in[0]);
  const float* w = reinterpret_cast<const float*>(d_in[1]);
  float* out = reinterpret_cast<float*>(d_out);
  qlin<<<B / R, TB>>>(x, w, out);
}